// round 2
// baseline (speedup 1.0000x reference)
#include <cuda_runtime.h>
#include <cstdint>
#include <cstddef>

#define BB 32
#define SS 2048
#define FF 768
#define HH 8
// rows = BB*SS = 65536, K-dim of final gemm = FF*HH = 6144

// ---------------- scratch (device globals; no allocation allowed) ----------
__device__ float  g_zatt [BB*HH*SS];   // [b][h][s]
__device__ float  g_zgate[BB*HH*SS];   // [b][h][s]
__device__ float2 g_wdup [BB*SS*HH];   // [b][s][h], (w,w) duplicated
__device__ float  g_pooled[BB*FF*HH];  // [b][f*H+h]
__device__ float  g_wt   [FF*16];      // [f][att h0..7, gate h0..7]

// ---------------- f32x2 helpers -------------------------------------------
__device__ __forceinline__ void ffma2(unsigned long long& d,
                                      unsigned long long a,
                                      unsigned long long b) {
    asm("fma.rn.f32x2 %0, %1, %2, %0;" : "+l"(d) : "l"(a), "l"(b));
}
__device__ __forceinline__ unsigned long long pack2(float lo, float hi) {
    unsigned long long r;
    asm("mov.b64 %0, {%1, %2};" : "=l"(r) : "f"(lo), "f"(hi));
    return r;
}
__device__ __forceinline__ float2 unpack2(unsigned long long v) {
    float2 f;
    asm("mov.b64 {%0, %1}, %2;" : "=f"(f.x), "=f"(f.y) : "l"(v));
    return f;
}

// ---------------- K0: prep (transpose W, zero pooled, init out with bias) --
__global__ void k_prep(const float* __restrict__ Watt,
                       const float* __restrict__ Wgate,
                       const float* __restrict__ bout,
                       float* __restrict__ out) {
    int i = blockIdx.x * blockDim.x + threadIdx.x;
    int stride = gridDim.x * blockDim.x;
    for (int idx = i; idx < FF * 16; idx += stride) {
        int f = idx >> 4, c = idx & 15;
        g_wt[idx] = (c < 8) ? Watt[c * FF + f] : Wgate[(c - 8) * FF + f];
    }
    for (int idx = i; idx < BB * FF * HH; idx += stride) g_pooled[idx] = 0.f;
    for (int idx = i; idx < BB * FF; idx += stride) out[idx] = bout[idx % FF];
}

// ---------------- K1: logits z_att/z_gate  [b][h][s] -----------------------
// 256 rows per CTA (one row per thread), full W (48KB) + x tile (33.8KB) in smem
__global__ void __launch_bounds__(256) k_logits(const float* __restrict__ x) {
    extern __shared__ float sm[];
    float* wsm = sm;                 // FF*16 = 12288 floats
    float* smx = sm + FF * 16;       // 256*33 = 8448 floats
    const int tid = threadIdx.x;

    // load W (already [f][16] laid out) — coalesced float4 copy
    {
        const float4* src = (const float4*)g_wt;
        float4* dst = (float4*)wsm;
        #pragma unroll
        for (int i = tid; i < FF * 4; i += 256) dst[i] = src[i];
    }

    const int rowbase = blockIdx.x * 256;
    const int b = rowbase / SS;          // 256 | 2048 → whole CTA same batch
    const int sloc = (rowbase % SS) + tid;

    unsigned long long acc[8];
    #pragma unroll
    for (int i = 0; i < 8; i++) acc[i] = 0ULL;

    for (int chunk = 0; chunk < FF / 32; chunk++) {
        __syncthreads();   // covers W-load on iter0 and smx reuse afterwards
        const int fbase = chunk * 32;
        // stage x tile: 256 rows x 32 f, padded stride 33 (conflict-free)
        #pragma unroll
        for (int it = 0; it < 8; it++) {
            int q = tid + it * 256;          // float4 index in tile
            int row = q >> 3, fq = q & 7;
            float4 v = *(const float4*)(x + (size_t)(rowbase + row) * FF + fbase + fq * 4);
            float* d = smx + row * 33 + fq * 4;
            d[0] = v.x; d[1] = v.y; d[2] = v.z; d[3] = v.w;
        }
        __syncthreads();

        const float* myrow = smx + tid * 33;
        #pragma unroll 8
        for (int fl = 0; fl < 32; fl++) {
            float xv = myrow[fl];
            unsigned long long xd = pack2(xv, xv);
            const ulonglong2* wrow = (const ulonglong2*)(wsm + (size_t)(fbase + fl) * 16);
            ulonglong2 w0 = wrow[0];   // att h0..3 (2 packed pairs)
            ulonglong2 w1 = wrow[1];   // att h4..7
            ulonglong2 w2 = wrow[2];   // gate h0..3
            ulonglong2 w3 = wrow[3];   // gate h4..7
            ffma2(acc[0], xd, w0.x); ffma2(acc[1], xd, w0.y);
            ffma2(acc[2], xd, w1.x); ffma2(acc[3], xd, w1.y);
            ffma2(acc[4], xd, w2.x); ffma2(acc[5], xd, w2.y);
            ffma2(acc[6], xd, w3.x); ffma2(acc[7], xd, w3.y);
        }
    }

    // write logits [b][h][s] (coalesced over tid = consecutive s)
    const size_t zbase = (size_t)b * HH * SS + sloc;
    #pragma unroll
    for (int j = 0; j < 4; j++) {
        float2 v = unpack2(acc[j]);
        g_zatt[zbase + (size_t)(2 * j) * SS]     = v.x;
        g_zatt[zbase + (size_t)(2 * j + 1) * SS] = v.y;
    }
    #pragma unroll
    for (int j = 0; j < 4; j++) {
        float2 v = unpack2(acc[4 + j]);
        g_zgate[zbase + (size_t)(2 * j) * SS]     = v.x;
        g_zgate[zbase + (size_t)(2 * j + 1) * SS] = v.y;
    }
}

// ---------------- K2: softmax (over s) * sigmoid → wdup [b][s][h] ----------
__global__ void __launch_bounds__(256) k_softmax(const float* __restrict__ bgate) {
    const int bh = blockIdx.x;              // 0..255
    const int b = bh >> 3, h = bh & 7;
    const float* za = g_zatt  + (size_t)bh * SS;
    const float* zg = g_zgate + (size_t)bh * SS;
    const int tid = threadIdx.x;
    const int lane = tid & 31, wid = tid >> 5;

    __shared__ float redm[9];
    __shared__ float reds[9];

    float zs[8], gs[8];
    float m = -3.4e38f;
    #pragma unroll
    for (int i = 0; i < 8; i++) {
        int s = tid + i * 256;
        zs[i] = za[s];
        gs[i] = zg[s];
        m = fmaxf(m, zs[i]);
    }
    #pragma unroll
    for (int o = 16; o > 0; o >>= 1) m = fmaxf(m, __shfl_xor_sync(0xffffffffu, m, o));
    if (lane == 0) redm[wid] = m;
    __syncthreads();
    if (tid == 0) {
        float t = redm[0];
        #pragma unroll
        for (int w = 1; w < 8; w++) t = fmaxf(t, redm[w]);
        redm[8] = t;
    }
    __syncthreads();
    m = redm[8];

    float p[8];
    float sum = 0.f;
    #pragma unroll
    for (int i = 0; i < 8; i++) { p[i] = expf(zs[i] - m); sum += p[i]; }
    #pragma unroll
    for (int o = 16; o > 0; o >>= 1) sum += __shfl_xor_sync(0xffffffffu, sum, o);
    if (lane == 0) reds[wid] = sum;
    __syncthreads();
    if (tid == 0) {
        float t = 0.f;
        #pragma unroll
        for (int w = 0; w < 8; w++) t += reds[w];
        reds[8] = t;
    }
    __syncthreads();
    const float inv = 1.f / reds[8];
    const float bg = bgate[h];

    #pragma unroll
    for (int i = 0; i < 8; i++) {
        int s = tid + i * 256;
        float g = 1.f / (1.f + expf(-(gs[i] + bg)));
        float w = p[i] * inv * g;
        g_wdup[((size_t)b * SS + s) * HH + h] = make_float2(w, w);
    }
}

// ---------------- K3: pooled[b][f*H+h] += sum_s w * x -----------------------
// grid (16 s-chunks, 32 b), 192 threads (thread owns 4 consecutive f = all 768)
__global__ void __launch_bounds__(192) k_pool(const float* __restrict__ x) {
    __shared__ __align__(16) float2 ws[128 * 8];  // [s_local][h]  8KB
    __shared__ float dump[32 * 193];              // transpose buffer 24.7KB
    const int b = blockIdx.y, sc = blockIdx.x;
    const int tid = threadIdx.x;
    const int sbase = sc * 128;

    // stage duplicated w chunk (contiguous → coalesced)
    {
        const float2* wsrc = g_wdup + ((size_t)b * SS + sbase) * HH;
        for (int i = tid; i < 128 * 8; i += 192) ws[i] = wsrc[i];
    }
    __syncthreads();

    unsigned long long acc[16];   // acc[h*2+j]: (f0+2j, f0+2j+1) partial for head h
    #pragma unroll
    for (int i = 0; i < 16; i++) acc[i] = 0ULL;

    const float* xb = x + ((size_t)b * SS + sbase) * FF + tid * 4;
    #pragma unroll 4
    for (int sl = 0; sl < 128; sl++) {
        float4 xv = *(const float4*)(xb + (size_t)sl * FF);
        unsigned long long x01 = pack2(xv.x, xv.y);
        unsigned long long x23 = pack2(xv.z, xv.w);
        const ulonglong2* wrow = (const ulonglong2*)(ws + sl * 8);
        ulonglong2 wa = wrow[0], wb = wrow[1], wc = wrow[2], wd = wrow[3];
        ffma2(acc[0],  x01, wa.x); ffma2(acc[1],  x23, wa.x);
        ffma2(acc[2],  x01, wa.y); ffma2(acc[3],  x23, wa.y);
        ffma2(acc[4],  x01, wb.x); ffma2(acc[5],  x23, wb.x);
        ffma2(acc[6],  x01, wb.y); ffma2(acc[7],  x23, wb.y);
        ffma2(acc[8],  x01, wc.x); ffma2(acc[9],  x23, wc.x);
        ffma2(acc[10], x01, wc.y); ffma2(acc[11], x23, wc.y);
        ffma2(acc[12], x01, wd.x); ffma2(acc[13], x23, wd.x);
        ffma2(acc[14], x01, wd.y); ffma2(acc[15], x23, wd.y);
    }

    // transpose through smem so atomics are coalesced.
    // value for local k-index i = fj*8 + h (global k = tid*32 + i) at dump[i*193 + tid]
    #pragma unroll
    for (int h = 0; h < 8; h++) {
        float2 v0 = unpack2(acc[h * 2]);       // f0, f0+1
        float2 v1 = unpack2(acc[h * 2 + 1]);   // f0+2, f0+3
        dump[(0 * 8 + h) * 193 + tid] = v0.x;
        dump[(1 * 8 + h) * 193 + tid] = v0.y;
        dump[(2 * 8 + h) * 193 + tid] = v1.x;
        dump[(3 * 8 + h) * 193 + tid] = v1.y;
    }
    __syncthreads();
    float* pb = g_pooled + (size_t)b * FF * HH;
    #pragma unroll
    for (int j = 0; j < 32; j++) {
        int k = j * 192 + tid;
        atomicAdd(pb + k, dump[(k & 31) * 193 + (k >> 5)]);
    }
}

// ---------------- K4: out[b][j] += pooled[b][:] . W_out[j][:] ---------------
// grid (16 k-tiles of 384, 12 j-tiles of 64), 256 threads; thread = 2b x 4j
__global__ void __launch_bounds__(256) k_out(const float* __restrict__ Wout,
                                             float* __restrict__ out) {
    __shared__ float sp[32 * 33];
    __shared__ float sw[64 * 33];
    const int kt = blockIdx.x, jt = blockIdx.y;
    const int kb = kt * 384, jb = jt * 64;
    const int tid = threadIdx.x;
    const int jg = tid & 15, bg = tid >> 4;
    const int j0 = jb + jg * 4, b0 = bg * 2;

    float acc[2][4] = {{0.f, 0.f, 0.f, 0.f}, {0.f, 0.f, 0.f, 0.f}};

    for (int kc = 0; kc < 384; kc += 32) {
        __syncthreads();
        #pragma unroll
        for (int it = 0; it < 4; it++) {
            int idx = tid + it * 256;
            int bb = idx >> 5, k = idx & 31;
            sp[bb * 33 + k] = g_pooled[(size_t)bb * (FF * HH) + kb + kc + k];
        }
        #pragma unroll
        for (int it = 0; it < 8; it++) {
            int idx = tid + it * 256;
            int j = idx >> 5, k = idx & 31;
            sw[j * 33 + k] = Wout[(size_t)(jb + j) * (FF * HH) + kb + kc + k];
        }
        __syncthreads();
        #pragma unroll 8
        for (int k = 0; k < 32; k++) {
            float p0 = sp[b0 * 33 + k];
            float p1 = sp[(b0 + 1) * 33 + k];
            #pragma unroll
            for (int jj = 0; jj < 4; jj++) {
                float w = sw[(jg * 4 + jj) * 33 + k];
                acc[0][jj] += p0 * w;
                acc[1][jj] += p1 * w;
            }
        }
    }
    #pragma unroll
    for (int i = 0; i < 2; i++)
        #pragma unroll
        for (int jj = 0; jj < 4; jj++)
            atomicAdd(out + (size_t)(b0 + i) * FF + j0 + jj, acc[i][jj]);
}

// ---------------- launch ----------------------------------------------------
extern "C" void kernel_launch(void* const* d_in, const int* in_sizes, int n_in,
                              void* d_out, int out_size) {
    (void)in_sizes; (void)n_in; (void)out_size;
    const float* x     = (const float*)d_in[0];
    const float* Watt  = (const float*)d_in[1];
    // d_in[2] = b_att : constant over s → cancels inside softmax, unused
    const float* Wgate = (const float*)d_in[3];
    const float* bgate = (const float*)d_in[4];
    const float* Wout  = (const float*)d_in[5];
    const float* bout  = (const float*)d_in[6];
    float* out = (float*)d_out;

    const int k1_smem = (FF * 16 + 256 * 33) * (int)sizeof(float);  // 82944 B
    cudaFuncSetAttribute(k_logits, cudaFuncAttributeMaxDynamicSharedMemorySize, k1_smem);

    k_prep<<<128, 256>>>(Watt, Wgate, bout, out);
    k_logits<<<(BB * SS) / 256, 256, k1_smem>>>(x);
    k_softmax<<<BB * HH, 256>>>(bgate);
    k_pool<<<dim3(16, BB), 192>>>(x);
    k_out<<<dim3(16, 12), 256>>>(Wout, out);
}